// round 9
// baseline (speedup 1.0000x reference)
#include <cuda_runtime.h>

// Problem constants (fixed by setup_inputs)
#define V_N     500000
#define NF_N    1000000
#define KDEG    7
#define NREP    4

#define NV3     (3*V_N)            // 1,500,000 floats
#define NF3     (3*NF_N)           // 3,000,000 floats
#define FACES_OUT_BASE  (NREP*NV3) // 6,000,000
#define SCALAR_BASE     (FACES_OUT_BASE + NREP*NF3) // 18,000,000

#define NV4     (NV3/4)            // 375,000 float4
#define NF4     (NF3/4)            // 750,000 int4

#define TPB          256
#define LOSS_BLOCKS  ((V_N + TPB - 1) / TPB)   // 1954
#define FACES_BLOCKS ((NF4 + TPB - 1) / TPB)   // 2930
#define VERTS_BLOCKS ((NV4 + TPB - 1) / TPB)   // 1465

// Scratch (rebuilt every call)
__device__ int    g_row_start[V_N + 1];
__device__ float4 g_pverts[V_N];   // vertices + center, 16B-padded for 1-wf gathers

// ---------------------------------------------------------------------------
// Kernel 1 (combo): prep + faces_rep + verts_rep, all independent streams.
//   [0, prep_blocks)   : zero scalars / pad pverts / build CSR row starts
//   [.., +FACES_BLOCKS): faces_rep (int4 -> float4 x4)
//   [.., end)          : verts_rep (float4 + center x4)
// prep's latency-bound pointer work hides under the reps' store bandwidth.
// ---------------------------------------------------------------------------
__global__ void __launch_bounds__(TPB)
combo_kernel(const float* __restrict__ vertices,
             const float* __restrict__ center,
             const int*   __restrict__ lap_rows, int nnz_e, int prep_blocks,
             const int4*  __restrict__ faces4,
             float* __restrict__ out) {
    const int b = blockIdx.x;

    // ======================= PREP BRANCH =======================
    if (b < prep_blocks) {
        int i = b * TPB + threadIdx.x;
        if (i < 4) out[SCALAR_BASE + i] = 0.0f;

        if (i < V_N) {
            float4 p;
            p.x = vertices[3*i]     + center[0];
            p.y = vertices[3*i + 1] + center[1];
            p.z = vertices[3*i + 2] + center[2];
            p.w = 0.f;
            g_pverts[i] = p;
        }

        int base = i * 4;
        if (base >= nnz_e) return;

        int4 r4 = *reinterpret_cast<const int4*>(lap_rows + base);
        int rr[4] = { r4.x, r4.y, r4.z, r4.w };
        int rp = (base == 0) ? -1 : __ldg(&lap_rows[base - 1]);

        #pragma unroll
        for (int t = 0; t < 4; ++t) {
            int j = base + t;
            if (j >= nnz_e) break;
            int r = rr[t];
            for (int r2 = rp + 1; r2 <= r; ++r2) g_row_start[r2] = j;
            rp = r;
        }
        if (base + 4 >= nnz_e) {                   // last chunk: fill tail
            for (int r2 = rp + 1; r2 <= V_N; ++r2) g_row_start[r2] = nnz_e;
        }
        return;
    }

    // ======================= FACES_REP BRANCH =======================
    if (b < prep_blocks + FACES_BLOCKS) {
        int i = (b - prep_blocks) * TPB + threadIdx.x;
        if (i >= NF4) return;
        int4 f = faces4[i];
        float4 v = make_float4((float)f.x, (float)f.y, (float)f.z, (float)f.w);
        float4* fo = (float4*)out + FACES_OUT_BASE / 4;
        fo[i]           = v;
        fo[i +   NF4]   = v;
        fo[i + 2*NF4]   = v;
        fo[i + 3*NF4]   = v;
        return;
    }

    // ======================= VERTS_REP BRANCH =======================
    {
        int i = (b - prep_blocks - FACES_BLOCKS) * TPB + threadIdx.x;
        if (i >= NV4) return;
        float cc[6];
        cc[0] = center[0]; cc[1] = center[1]; cc[2] = center[2];
        cc[3] = cc[0]; cc[4] = cc[1]; cc[5] = cc[2];

        int m = i % 3;                 // (4*i) mod 3 == i mod 3
        float4 v = ((const float4*)vertices)[i];
        v.x += cc[m];
        v.y += cc[m + 1];
        v.z += cc[m + 2];
        v.w += cc[m];
        float4* o4 = (float4*)out;
        o4[i]            = v;
        o4[i +   NV4]    = v;
        o4[i + 2*NV4]    = v;
        o4[i + 3*NV4]    = v;
    }
}

// ---------------------------------------------------------------------------
// Kernel 2: per-vertex fused losses only (gathers own the whole machine).
// ---------------------------------------------------------------------------
__global__ void __launch_bounds__(TPB)
loss_kernel(const int*   __restrict__ lap_cols,
            const float* __restrict__ lap_vals,
            const int*   __restrict__ k_cols,
            const float* __restrict__ k_vals,
            float* __restrict__ out) {
    const int v = blockIdx.x * TPB + threadIdx.x;
    const float4* __restrict__ pverts = g_pverts;

    float lap_c = 0.0f, hex_c = 0.0f;
    if (v < V_N) {
        // ---- k SpMV (7 entries per row, one 16B gather per entry) ----
        float ax = 0.f, ay = 0.f, az = 0.f;
        const int kb = v * KDEG;
        #pragma unroll
        for (int j = 0; j < KDEG; ++j) {
            int    c = __ldg(&k_cols[kb + j]);
            float  w = __ldg(&k_vals[kb + j]);
            float4 p = __ldg(&pverts[c]);
            ax += w * p.x;
            ay += w * p.y;
            az += w * p.z;
        }
        hex_c = ax*ax + ay*ay + az*az;

        // ---- lap SpMV: known trip count, one 16B gather per entry ----
        const int s = g_row_start[v];
        const int e = g_row_start[v + 1];
        float4 pv = __ldg(&pverts[v]);
        float sx = -pv.x, sy = -pv.y, sz = -pv.z;
        #pragma unroll 4
        for (int j = s; j < e; ++j) {
            int    c = __ldg(&lap_cols[j]);
            float  w = __ldg(&lap_vals[j]);
            float4 p = __ldg(&pverts[c]);
            sx += w * p.x;
            sy += w * p.y;
            sz += w * p.z;
        }
        lap_c = sqrtf(sx*sx + sy*sy + sz*sz);
    }

    // ---- block reduction ----
    const unsigned FULL = 0xFFFFFFFFu;
    #pragma unroll
    for (int off = 16; off > 0; off >>= 1) {
        lap_c += __shfl_down_sync(FULL, lap_c, off);
        hex_c += __shfl_down_sync(FULL, hex_c, off);
    }
    __shared__ float s_red[16];
    int lane = threadIdx.x & 31;
    int wid  = threadIdx.x >> 5;
    if (lane == 0) { s_red[wid] = lap_c; s_red[8 + wid] = hex_c; }
    __syncthreads();
    if (wid == 0) {
        float l = (lane < (TPB >> 5)) ? s_red[lane]     : 0.f;
        float h = (lane < (TPB >> 5)) ? s_red[8 + lane] : 0.f;
        #pragma unroll
        for (int off = 4; off > 0; off >>= 1) {
            l += __shfl_down_sync(FULL, l, off);
            h += __shfl_down_sync(FULL, h, off);
        }
        if (lane == 0) {
            const float inv = 1.0f / (float)V_N;
            atomicAdd(out + SCALAR_BASE,     l * inv);
            atomicAdd(out + SCALAR_BASE + 1, h * inv);
        }
    }
}

// ---------------------------------------------------------------------------
// Launch. Inputs (metadata order):
//   0 vertices, 1 center, 2 lap_rows, 3 lap_cols, 4 lap_vals,
//   5 k_rows, 6 k_cols, 7 k_vals, 8 faces, 9 total_num
// ---------------------------------------------------------------------------
extern "C" void kernel_launch(void* const* d_in, const int* in_sizes, int n_in,
                              void* d_out, int out_size) {
    const float* vertices = (const float*)d_in[0];
    const float* center   = (const float*)d_in[1];
    const int*   lap_rows = (const int*)  d_in[2];
    const int*   lap_cols = (const int*)  d_in[3];
    const float* lap_vals = (const float*)d_in[4];
    const int*   k_cols   = (const int*)  d_in[6];
    const float* k_vals   = (const float*)d_in[7];
    const int*   faces    = (const int*)  d_in[8];
    float* out = (float*)d_out;

    const int nnz_e = in_sizes[2] - V_N;  // off-diagonal (sorted) entry count
    int prep_threads = (nnz_e + 3) / 4;
    if (prep_threads < V_N) prep_threads = V_N;
    const int prep_blocks = (prep_threads + TPB - 1) / TPB;
    const int combo_blocks = prep_blocks + FACES_BLOCKS + VERTS_BLOCKS;

    combo_kernel<<<combo_blocks, TPB>>>(vertices, center,
                                        lap_rows, nnz_e, prep_blocks,
                                        (const int4*)faces, out);
    loss_kernel<<<LOSS_BLOCKS, TPB>>>(lap_cols, lap_vals,
                                      k_cols, k_vals, out);
}

// round 10
// speedup vs baseline: 1.0283x; 1.0283x over previous
#include <cuda_runtime.h>

// Problem constants (fixed by setup_inputs)
#define V_N     500000
#define NF_N    1000000
#define KDEG    7
#define NREP    4

#define NV3     (3*V_N)            // 1,500,000 floats
#define NF3     (3*NF_N)           // 3,000,000 floats
#define FACES_OUT_BASE  (NREP*NV3) // 6,000,000
#define SCALAR_BASE     (FACES_OUT_BASE + NREP*NF3) // 18,000,000

#define NV4     (NV3/4)            // 375,000 float4
#define NF4     (NF3/4)            // 750,000 int4
#define PV4     (V_N/4)            // 125,000 pad chunks (4 verts each)

#define TPB          256
#define LOSS_BLOCKS  ((V_N + TPB - 1) / TPB)   // 1954
#define FACES_BLOCKS ((NF4 + TPB - 1) / TPB)   // 2930
#define VERTS_BLOCKS ((NV4 + TPB - 1) / TPB)   // 1465
#define TOTAL_BLOCKS (LOSS_BLOCKS + FACES_BLOCKS + VERTS_BLOCKS)

// Scratch (rebuilt every call)
__device__ int    g_row_start[V_N + 1];
__device__ float4 g_pverts[V_N];   // vertices + center, 16B-padded for 1-wf gathers

// ---------------------------------------------------------------------------
// Prep: zero scalars + pad pverts (4 verts/thread, coalesced float4) + build
// CSR row starts (int4 chunks; previous row via warp shuffle, lane0 loads).
// ---------------------------------------------------------------------------
__global__ void __launch_bounds__(TPB)
prep_kernel(const float4* __restrict__ verts4,
            const float*  __restrict__ center,
            const int*    __restrict__ lap_rows, int nnz_e,
            float* __restrict__ out) {
    const int i = blockIdx.x * TPB + threadIdx.x;
    if (i < 4) out[SCALAR_BASE + i] = 0.0f;

    // ---- rowptr chunk load + warp-shuffle of previous row (warp-uniform) ----
    const int base = i * 4;
    const bool act = (base < nnz_e);
    int4 r4 = make_int4(0, 0, 0, 0);
    if (act) r4 = *(const int4*)(lap_rows + base);          // safe: tail exists
    const int prev_w = __shfl_up_sync(0xFFFFFFFFu, r4.w, 1);

    // ---- pad 4 vertices per thread ----
    if (i < PV4) {
        const float c0 = center[0], c1 = center[1], c2 = center[2];
        float4 a = verts4[3*i], bq = verts4[3*i + 1], cq = verts4[3*i + 2];
        g_pverts[4*i    ] = make_float4(a.x  + c0, a.y  + c1, a.z  + c2, 0.f);
        g_pverts[4*i + 1] = make_float4(a.w  + c0, bq.x + c1, bq.y + c2, 0.f);
        g_pverts[4*i + 2] = make_float4(bq.z + c0, bq.w + c1, cq.x + c2, 0.f);
        g_pverts[4*i + 3] = make_float4(cq.y + c0, cq.z + c1, cq.w + c2, 0.f);
    }

    if (!act) return;

    const int lane = threadIdx.x & 31;
    int rp;
    if (lane == 0) rp = (base == 0) ? -1 : __ldg(&lap_rows[base - 1]);
    else           rp = prev_w;   // lane>0 => neighbor chunk in-range => valid

    int rr[4] = { r4.x, r4.y, r4.z, r4.w };
    #pragma unroll
    for (int t = 0; t < 4; ++t) {
        int j = base + t;
        if (j >= nnz_e) break;
        int r = rr[t];
        for (int r2 = rp + 1; r2 <= r; ++r2) g_row_start[r2] = j;
        rp = r;
    }
    if (base + 4 >= nnz_e) {                       // last chunk: fill tail
        for (int r2 = rp + 1; r2 <= V_N; ++r2) g_row_start[r2] = nnz_e;
    }
}

// ---------------------------------------------------------------------------
// Fused kernel (R7 config, measured 58.8us): block-range dispatch.
//   [0, LOSS_BLOCKS)      -> per-vertex fused losses (16B gathers)
//   [.., +FACES_BLOCKS)   -> faces_rep (int4 -> float4 x4)
//   [.., TOTAL_BLOCKS)    -> verts_rep (float4 + center x4)
// Loss blocks at lowest indices (wave 1); store-bound rep blocks backfill.
// ---------------------------------------------------------------------------
__global__ void __launch_bounds__(TPB)
fused_kernel(const float* __restrict__ vertices,
             const float* __restrict__ center,
             const int*   __restrict__ lap_cols,
             const float* __restrict__ lap_vals,
             const int*   __restrict__ k_cols,
             const float* __restrict__ k_vals,
             const int4*  __restrict__ faces4,
             float* __restrict__ out) {
    const int b = blockIdx.x;

    // ======================= LOSS BRANCH =======================
    if (b < LOSS_BLOCKS) {
        const int v = b * TPB + threadIdx.x;
        const float4* __restrict__ pverts = g_pverts;

        float lap_c = 0.0f, hex_c = 0.0f;
        if (v < V_N) {
            // ---- k SpMV (7 entries per row, one 16B gather per entry) ----
            float ax = 0.f, ay = 0.f, az = 0.f;
            const int kb = v * KDEG;
            #pragma unroll
            for (int j = 0; j < KDEG; ++j) {
                int    c = __ldg(&k_cols[kb + j]);
                float  w = __ldg(&k_vals[kb + j]);
                float4 p = __ldg(&pverts[c]);
                ax += w * p.x;
                ay += w * p.y;
                az += w * p.z;
            }
            hex_c = ax*ax + ay*ay + az*az;

            // ---- lap SpMV: known trip count, one 16B gather per entry ----
            const int s = g_row_start[v];
            const int e = g_row_start[v + 1];
            float4 pv = __ldg(&pverts[v]);
            float sx = -pv.x, sy = -pv.y, sz = -pv.z;
            #pragma unroll 4
            for (int j = s; j < e; ++j) {
                int    c = __ldg(&lap_cols[j]);
                float  w = __ldg(&lap_vals[j]);
                float4 p = __ldg(&pverts[c]);
                sx += w * p.x;
                sy += w * p.y;
                sz += w * p.z;
            }
            lap_c = sqrtf(sx*sx + sy*sy + sz*sz);
        }

        // ---- block reduction ----
        const unsigned FULL = 0xFFFFFFFFu;
        #pragma unroll
        for (int off = 16; off > 0; off >>= 1) {
            lap_c += __shfl_down_sync(FULL, lap_c, off);
            hex_c += __shfl_down_sync(FULL, hex_c, off);
        }
        __shared__ float s_red[16];
        int lane = threadIdx.x & 31;
        int wid  = threadIdx.x >> 5;
        if (lane == 0) { s_red[wid] = lap_c; s_red[8 + wid] = hex_c; }
        __syncthreads();
        if (wid == 0) {
            float l = (lane < (TPB >> 5)) ? s_red[lane]     : 0.f;
            float h = (lane < (TPB >> 5)) ? s_red[8 + lane] : 0.f;
            #pragma unroll
            for (int off = 4; off > 0; off >>= 1) {
                l += __shfl_down_sync(FULL, l, off);
                h += __shfl_down_sync(FULL, h, off);
            }
            if (lane == 0) {
                const float inv = 1.0f / (float)V_N;
                atomicAdd(out + SCALAR_BASE,     l * inv);
                atomicAdd(out + SCALAR_BASE + 1, h * inv);
            }
        }
        return;
    }

    // ======================= FACES_REP BRANCH =======================
    if (b < LOSS_BLOCKS + FACES_BLOCKS) {
        int i = (b - LOSS_BLOCKS) * TPB + threadIdx.x;
        if (i >= NF4) return;
        int4 f = faces4[i];
        float4 v = make_float4((float)f.x, (float)f.y, (float)f.z, (float)f.w);
        float4* fo = (float4*)out + FACES_OUT_BASE / 4;
        fo[i]           = v;
        fo[i +   NF4]   = v;
        fo[i + 2*NF4]   = v;
        fo[i + 3*NF4]   = v;
        return;
    }

    // ======================= VERTS_REP BRANCH =======================
    {
        int i = (b - LOSS_BLOCKS - FACES_BLOCKS) * TPB + threadIdx.x;
        if (i >= NV4) return;
        float cc[6];
        cc[0] = center[0]; cc[1] = center[1]; cc[2] = center[2];
        cc[3] = cc[0]; cc[4] = cc[1]; cc[5] = cc[2];

        int m = i % 3;                 // (4*i) mod 3 == i mod 3
        float4 v = ((const float4*)vertices)[i];
        v.x += cc[m];
        v.y += cc[m + 1];
        v.z += cc[m + 2];
        v.w += cc[m];
        float4* o4 = (float4*)out;
        o4[i]            = v;
        o4[i +   NV4]    = v;
        o4[i + 2*NV4]    = v;
        o4[i + 3*NV4]    = v;
    }
}

// ---------------------------------------------------------------------------
// Launch. Inputs (metadata order):
//   0 vertices, 1 center, 2 lap_rows, 3 lap_cols, 4 lap_vals,
//   5 k_rows, 6 k_cols, 7 k_vals, 8 faces, 9 total_num
// ---------------------------------------------------------------------------
extern "C" void kernel_launch(void* const* d_in, const int* in_sizes, int n_in,
                              void* d_out, int out_size) {
    const float* vertices = (const float*)d_in[0];
    const float* center   = (const float*)d_in[1];
    const int*   lap_rows = (const int*)  d_in[2];
    const int*   lap_cols = (const int*)  d_in[3];
    const float* lap_vals = (const float*)d_in[4];
    const int*   k_cols   = (const int*)  d_in[6];
    const float* k_vals   = (const float*)d_in[7];
    const int*   faces    = (const int*)  d_in[8];
    float* out = (float*)d_out;

    const int nnz_e = in_sizes[2] - V_N;  // off-diagonal (sorted) entry count
    int prep_threads = (nnz_e + 3) / 4;
    if (prep_threads < PV4) prep_threads = PV4;

    prep_kernel<<<(prep_threads + TPB - 1) / TPB, TPB>>>(
        (const float4*)vertices, center, lap_rows, nnz_e, out);
    fused_kernel<<<TOTAL_BLOCKS, TPB>>>(vertices, center,
                                        lap_cols, lap_vals,
                                        k_cols, k_vals,
                                        (const int4*)faces, out);
}